// round 11
// baseline (speedup 1.0000x reference)
#include <cuda_runtime.h>
#include <cstdint>

#define D 128
#define C 64
#define EPSF 1e-5f
#define TGT 32              // targets per CTA -> grid = 16384/32 = 512
#define RS 132              // row stride (floats) for xs and qs: conflict-free

// q[c][j] = EPS - prototype[c][j]   (device scratch; allocations forbidden)
__device__ float g_q[C * D];

__device__ __forceinline__ void add_f32x2(unsigned long long& d,
                                          unsigned long long a,
                                          unsigned long long b) {
    asm("add.rn.f32x2 %0, %1, %2;" : "=l"(d) : "l"(a), "l"(b));
}
__device__ __forceinline__ void fma_f32x2(unsigned long long& d,
                                          unsigned long long a,
                                          unsigned long long b) {
    asm("fma.rn.f32x2 %0, %1, %2, %0;" : "+l"(d) : "l"(a), "l"(b));
}
__device__ __forceinline__ void unpack2(float& lo, float& hi,
                                        unsigned long long v) {
    asm("mov.b64 {%0, %1}, %2;" : "=f"(lo), "=f"(hi) : "l"(v));
}

// ---------------------------------------------------------------------------
// Kernel 1 (unchanged, proven): one CTA per class; gather row list, coalesced
// register accumulation, writes q = EPS - sum/cnt'. CTA0 zeroes out.
// ---------------------------------------------------------------------------
__global__ __launch_bounds__(256) void k_accum(const float* __restrict__ x,
                                               const int* __restrict__ y,
                                               float* __restrict__ out,
                                               int m) {
    __shared__ unsigned short list[4096];
    __shared__ int cnt;
    __shared__ float partial[D];

    int tid = threadIdx.x;
    int c   = blockIdx.x;
    if (tid == 0) cnt = 0;
    if (c == 0 && tid == 0) out[0] = 0.0f;
    __syncthreads();

#pragma unroll 8
    for (int i = tid; i < m; i += 256) {
        if (y[i] == c) {
            int p = atomicAdd(&cnt, 1);
            if (p < 4096) list[p] = (unsigned short)i;
        }
    }
    __syncthreads();
    int n = cnt < 4096 ? cnt : 4096;

    int j    = tid & (D - 1);
    int half = tid >> 7;
    float acc = 0.0f;
#pragma unroll 4
    for (int k = half; k < n; k += 2) {
        acc += x[(size_t)list[k] * D + j];
    }
    if (half == 1) partial[j] = acc;
    __syncthreads();
    if (half == 0) {
        float tot = acc + partial[j];
        float fc  = (n == 0) ? 1.0f : (float)n;
        g_q[c * D + j] = EPSF - tot / fc;
    }
}

// ---------------------------------------------------------------------------
// Kernel 2: distances + log_softmax + NLL.
// block 128 = 4 warps. Warp w owns classes [16w, 16w+16).
// lane = c_idx*8 + t_idx: classes {16w + c_idx + 4cc}, targets {t_idx + 8k}.
// Per j4 per warp: 4 x-LDS + 4 q-LDS (conflict-free) serve 64 elements.
// Math: FADD2 + 2xLOP3 + FFMA2 = 2.0 instr/el, fma/alu pipes balanced.
// smem ~54.9KB -> 4 CTAs/SM; grid 512 fully resident in one wave.
// ---------------------------------------------------------------------------
extern __shared__ float dynsmem[];

__global__ __launch_bounds__(128, 4) void k_loss(const float* __restrict__ x,
                                                 const int* __restrict__ y,
                                                 float* __restrict__ out,
                                                 int m) {
    float* xs = dynsmem;            // TGT * 132 = 16.5 KB
    float* qs = xs + TGT * RS;      // C   * 132 = 33.8 KB
    __shared__ float spmax[16 * TGT];
    __shared__ float spsum[16 * TGT];
    __shared__ float sdy[TGT];

    int tid = threadIdx.x;
    int i0  = blockIdx.x * TGT;

    // stage x (32 x 128) into stride-132 rows, coalesced float4
    const float4* xg = (const float4*)(x + (size_t)(m + i0) * D);
#pragma unroll
    for (int k = 0; k < 8; k++) {
        int idx = tid + k * 128;            // 0..1023
        int r = idx >> 5, c4 = idx & 31;
        *(float4*)&xs[r * RS + c4 * 4] = xg[r * 32 + c4];
    }
    // stage q (64 x 128) into stride-132 rows
    const float4* qg = (const float4*)g_q;
#pragma unroll
    for (int k = 0; k < 16; k++) {
        int idx = tid + k * 128;            // 0..2047
        int r = idx >> 5, c4 = idx & 31;
        *(float4*)&qs[r * RS + c4 * 4] = qg[idx];
    }
    __syncthreads();

    int lane  = tid & 31;
    int w     = tid >> 5;                   // warp id 0..3
    int c_idx = lane >> 3;                  // 0..3
    int t_idx = lane & 7;                   // 0..7

    const ulonglong2* xr[4];
    const ulonglong2* qr[4];
#pragma unroll
    for (int k = 0; k < 4; k++)
        xr[k] = (const ulonglong2*)&xs[(t_idx + 8 * k) * RS];
#pragma unroll
    for (int cc = 0; cc < 4; cc++)
        qr[cc] = (const ulonglong2*)&qs[(w * 16 + c_idx + 4 * cc) * RS];

    unsigned long long acc[4][4];           // [target k][class cc], packed dims
#pragma unroll
    for (int k = 0; k < 4; k++)
#pragma unroll
        for (int cc = 0; cc < 4; cc++) acc[k][cc] = 0ull;

    const unsigned long long ABS2 = 0x7FFFFFFF7FFFFFFFull;

#pragma unroll 2
    for (int j4 = 0; j4 < D / 4; j4++) {
        ulonglong2 xv[4], qv[4];
#pragma unroll
        for (int k = 0; k < 4; k++)  xv[k]  = xr[k][j4];
#pragma unroll
        for (int cc = 0; cc < 4; cc++) qv[cc] = qr[cc][j4];
#pragma unroll
        for (int k = 0; k < 4; k++) {
#pragma unroll
            for (int cc = 0; cc < 4; cc++) {
                unsigned long long tA, tB;
                add_f32x2(tA, xv[k].x, qv[cc].x);     // t = x + (EPS - p)
                add_f32x2(tB, xv[k].y, qv[cc].y);
                fma_f32x2(acc[k][cc], tA, tA & ABS2); // acc += t * |t|
                fma_f32x2(acc[k][cc], tB, tB & ABS2);
            }
        }
    }

    // per-lane distances + partial softmax (per target, over lane's 4 classes)
    int sidx = w * 4 + c_idx;               // class-subset id 0..15
    float dist[4][4];
#pragma unroll
    for (int k = 0; k < 4; k++) {
        float pm = -1e30f;
#pragma unroll
        for (int cc = 0; cc < 4; cc++) {
            float lo, hi;
            unpack2(lo, hi, acc[k][cc]);
            float dv = (lo + hi) * (-1.0f / (float)D);
            dist[k][cc] = dv;
            pm = fmaxf(pm, dv);
        }
        spmax[sidx * TGT + t_idx + 8 * k] = pm;
    }
    __syncthreads();

#pragma unroll
    for (int k = 0; k < 4; k++) {
        int t = t_idx + 8 * k;
        float gm = -1e30f;
#pragma unroll
        for (int s = 0; s < 16; s++) gm = fmaxf(gm, spmax[s * TGT + t]);
        float se = 0.0f;
#pragma unroll
        for (int cc = 0; cc < 4; cc++) se += __expf(dist[k][cc] - gm);
        spsum[sidx * TGT + t] = se;

        int yc = y[m + i0 + t];
        int rel = yc - w * 16;
        if (rel >= 0 && rel < 16 && (rel & 3) == c_idx)
            sdy[t] = dist[k][rel >> 2];
    }
    __syncthreads();

    if (tid < TGT) {
        float tot = 0.0f, gm = -1e30f;
#pragma unroll
        for (int s = 0; s < 16; s++) {
            tot += spsum[s * TGT + tid];
            gm   = fmaxf(gm, spmax[s * TGT + tid]);
        }
        float v = -(sdy[tid] - gm - __logf(tot));
#pragma unroll
        for (int off = 16; off > 0; off >>= 1)
            v += __shfl_xor_sync(0xFFFFFFFFu, v, off);
        if (tid == 0) atomicAdd(out, v / (float)m);
    }
}

// ---------------------------------------------------------------------------
// launch
// ---------------------------------------------------------------------------
extern "C" void kernel_launch(void* const* d_in, const int* in_sizes, int n_in,
                              void* d_out, int out_size) {
    const float* x = (const float*)d_in[0];
    const int*   y = (const int*)d_in[1];
    int n = in_sizes[1];
    int m = n / 2;
    float* out = (float*)d_out;

    k_accum<<<C, 256>>>(x, y, out, m);

    size_t dynbytes = (size_t)((TGT + C) * RS) * sizeof(float);
    cudaFuncSetAttribute(k_loss, cudaFuncAttributeMaxDynamicSharedMemorySize,
                         (int)dynbytes);
    k_loss<<<m / TGT, 128, dynbytes>>>(x, y, out, m);
}

// round 12
// speedup vs baseline: 1.1853x; 1.1853x over previous
#include <cuda_runtime.h>
#include <cstdint>

#define D 128
#define C 64
#define EPSF 1e-5f
#define TGT 32              // targets per CTA -> grid = 16384/32 = 512
#define XS_STRIDE 132       // conflict-free row stride

// q[c][j] = EPS - prototype[c][j]   (device scratch; allocations forbidden)
__device__ float g_q[C * D];

__device__ __forceinline__ void add_f32x2(unsigned long long& d,
                                          unsigned long long a,
                                          unsigned long long b) {
    asm("add.rn.f32x2 %0, %1, %2;" : "=l"(d) : "l"(a), "l"(b));
}
__device__ __forceinline__ void fma_f32x2(unsigned long long& d,
                                          unsigned long long a,
                                          unsigned long long b) {
    asm("fma.rn.f32x2 %0, %1, %2, %0;" : "+l"(d) : "l"(a), "l"(b));
}
__device__ __forceinline__ void unpack2(float& lo, float& hi,
                                        unsigned long long v) {
    asm("mov.b64 {%0, %1}, %2;" : "=f"(lo), "=f"(hi) : "l"(v));
}

// ---------------------------------------------------------------------------
// Kernel 1: one CTA per class, block 512 = 4 row-streams.
// Gather row list (unrolled scan), then 4 parallel accumulation streams with
// unroll-8 MLP. Writes q = EPS - sum/cnt'. CTA0 zeroes out.
// ---------------------------------------------------------------------------
__global__ __launch_bounds__(512) void k_accum(const float* __restrict__ x,
                                               const int* __restrict__ y,
                                               float* __restrict__ out,
                                               int m) {
    __shared__ unsigned short list[4096];
    __shared__ int cnt;
    __shared__ float partial[4 * D];

    int tid = threadIdx.x;
    int c   = blockIdx.x;
    if (tid == 0) cnt = 0;
    if (c == 0 && tid == 0) out[0] = 0.0f;
    __syncthreads();

#pragma unroll 8
    for (int i = tid; i < m; i += 512) {
        if (y[i] == c) {
            int p = atomicAdd(&cnt, 1);
            if (p < 4096) list[p] = (unsigned short)i;
        }
    }
    __syncthreads();
    int n = cnt < 4096 ? cnt : 4096;

    int j  = tid & (D - 1);
    int st = tid >> 7;                 // stream 0..3
    float acc = 0.0f;
#pragma unroll 8
    for (int k = st; k < n; k += 4) {
        acc += x[(size_t)list[k] * D + j];
    }
    partial[st * D + j] = acc;
    __syncthreads();
    if (tid < D) {
        float tot = partial[j] + partial[D + j] + partial[2 * D + j]
                  + partial[3 * D + j];
        float fc  = (n == 0) ? 1.0f : (float)n;
        g_q[c * D + j] = EPSF - tot / fc;
    }
}

// ---------------------------------------------------------------------------
// Kernel 2: distances + log_softmax + NLL. R10 skeleton, split math mix.
// block 256 = 8 warps; warp w: classes [8w, 8w+8); lane = sub*16 + trow;
// each lane: targets {trow, trow+16}, classes {8w+4sub .. +3}.
// Per j4 per warp: 2 x-LDS + 4 q-LDS serve 32 elements.
// Math: FADD2 (fma 0.5/el) + 2xLOP3 |t| (alu 1/el) + FFMA2 (fma 0.5/el).
// ---------------------------------------------------------------------------
extern __shared__ float dynsmem[];

__global__ __launch_bounds__(256, 4) void k_loss(const float* __restrict__ x,
                                                 const int* __restrict__ y,
                                                 float* __restrict__ out,
                                                 int m) {
    float* xs = dynsmem;                   // 32 * 132 = 16.5 KB
    float* qs = xs + TGT * XS_STRIDE;      // 64 * 128 = 32 KB
    __shared__ float spmax[16 * TGT];
    __shared__ float spsum[16 * TGT];
    __shared__ float sdy[TGT];

    int tid = threadIdx.x;
    int i0  = blockIdx.x * TGT;

    // stage x target tile (32 x 128, coalesced float4)
    const float4* xg = (const float4*)(x + (size_t)(m + i0) * D);
#pragma unroll
    for (int k = 0; k < 4; k++) {
        int idx = tid + k * 256;
        int r = idx >> 5, c4 = idx & 31;
        *(float4*)&xs[r * XS_STRIDE + c4 * 4] = xg[r * 32 + c4];
    }
    // stage q
#pragma unroll
    for (int k = 0; k < 8; k++) {
        int idx = tid + k * 256;
        ((float4*)qs)[idx] = ((const float4*)g_q)[idx];
    }
    __syncthreads();

    int lane = tid & 31;
    int cg   = tid >> 5;                  // warp id 0..7
    int sub  = lane >> 4;                 // 0/1
    int trow = lane & 15;                 // 0..15
    int cb   = cg * 8 + sub * 4;          // first of lane's 4 classes
    int sidx = cg * 2 + sub;              // class-subset 0..15

    const ulonglong2* xr0 = (const ulonglong2*)&xs[trow * XS_STRIDE];
    const ulonglong2* xr1 = (const ulonglong2*)&xs[(trow + 16) * XS_STRIDE];
    const float* qb = &qs[cb * D];

    unsigned long long acc[4][2];         // [class][target], packed dim pairs
#pragma unroll
    for (int k = 0; k < 4; k++) { acc[k][0] = 0ull; acc[k][1] = 0ull; }

    const unsigned long long ABS2 = 0x7FFFFFFF7FFFFFFFull;

#pragma unroll 2
    for (int j4 = 0; j4 < D / 4; j4++) {
        ulonglong2 xv0 = xr0[j4];
        ulonglong2 xv1 = xr1[j4];
#pragma unroll
        for (int cc = 0; cc < 4; cc++) {
            ulonglong2 qv = *(const ulonglong2*)&qb[cc * D + j4 * 4];
            unsigned long long tA, tB, tE, tF;
            add_f32x2(tA, xv0.x, qv.x);          // target 0, dims 0-1
            add_f32x2(tB, xv0.y, qv.y);          // target 0, dims 2-3
            add_f32x2(tE, xv1.x, qv.x);          // target 1, dims 0-1
            add_f32x2(tF, xv1.y, qv.y);          // target 1, dims 2-3
            fma_f32x2(acc[cc][0], tA, tA & ABS2);
            fma_f32x2(acc[cc][0], tB, tB & ABS2);
            fma_f32x2(acc[cc][1], tE, tE & ABS2);
            fma_f32x2(acc[cc][1], tF, tF & ABS2);
        }
    }

    // unpack once, partial softmax over lane's 4 classes, both targets
    float dist[4][2];
    float pm0 = -1e30f, pm1 = -1e30f;
#pragma unroll
    for (int cc = 0; cc < 4; cc++) {
        float lo, hi;
        unpack2(lo, hi, acc[cc][0]);
        float d0 = (lo + hi) * (-1.0f / (float)D);
        unpack2(lo, hi, acc[cc][1]);
        float d1 = (lo + hi) * (-1.0f / (float)D);
        dist[cc][0] = d0; dist[cc][1] = d1;
        pm0 = fmaxf(pm0, d0);
        pm1 = fmaxf(pm1, d1);
    }
    spmax[sidx * TGT + trow]      = pm0;
    spmax[sidx * TGT + trow + 16] = pm1;
    __syncthreads();

    float g0 = -1e30f, g1 = -1e30f;
#pragma unroll
    for (int k = 0; k < 16; k++) {
        g0 = fmaxf(g0, spmax[k * TGT + trow]);
        g1 = fmaxf(g1, spmax[k * TGT + trow + 16]);
    }
    float se0 = 0.0f, se1 = 0.0f;
#pragma unroll
    for (int cc = 0; cc < 4; cc++) {
        se0 += __expf(dist[cc][0] - g0);
        se1 += __expf(dist[cc][1] - g1);
    }
    spsum[sidx * TGT + trow]      = se0;
    spsum[sidx * TGT + trow + 16] = se1;

    int yc0 = y[m + i0 + trow];
    if (yc0 >= cb && yc0 < cb + 4) sdy[trow] = dist[yc0 - cb][0];
    int yc1 = y[m + i0 + trow + 16];
    if (yc1 >= cb && yc1 < cb + 4) sdy[trow + 16] = dist[yc1 - cb][1];
    __syncthreads();

    if (tid < TGT) {
        float tot = 0.0f, gm = -1e30f;
#pragma unroll
        for (int k = 0; k < 16; k++) {
            tot += spsum[k * TGT + tid];
            gm   = fmaxf(gm, spmax[k * TGT + tid]);
        }
        float v = -(sdy[tid] - gm - __logf(tot));
#pragma unroll
        for (int off = 16; off > 0; off >>= 1)
            v += __shfl_xor_sync(0xFFFFFFFFu, v, off);
        if (tid == 0) atomicAdd(out, v / (float)m);
    }
}

// ---------------------------------------------------------------------------
// launch
// ---------------------------------------------------------------------------
extern "C" void kernel_launch(void* const* d_in, const int* in_sizes, int n_in,
                              void* d_out, int out_size) {
    const float* x = (const float*)d_in[0];
    const int*   y = (const int*)d_in[1];
    int n = in_sizes[1];
    int m = n / 2;
    float* out = (float*)d_out;

    k_accum<<<C, 512>>>(x, y, out, m);

    size_t dynbytes = (size_t)(TGT * XS_STRIDE + C * D) * sizeof(float);
    cudaFuncSetAttribute(k_loss, cudaFuncAttributeMaxDynamicSharedMemorySize,
                         (int)dynbytes);
    k_loss<<<m / TGT, 256, dynbytes>>>(x, y, out, m);
}

// round 13
// speedup vs baseline: 1.3769x; 1.1617x over previous
#include <cuda_runtime.h>
#include <cstdint>

#define D 128
#define C 64
#define EPSF 1e-5f
#define TGT 32              // targets per CTA -> grid = 16384/32 = 512
#define XS_STRIDE 132       // conflict-free row stride

// q[c][j] = EPS - prototype[c][j]   (device scratch; allocations forbidden)
__device__ float g_q[C * D];

__device__ __forceinline__ void add_f32x2(unsigned long long& d,
                                          unsigned long long a,
                                          unsigned long long b) {
    asm("add.rn.f32x2 %0, %1, %2;" : "=l"(d) : "l"(a), "l"(b));
}
__device__ __forceinline__ void unpack2(float& lo, float& hi,
                                        unsigned long long v) {
    asm("mov.b64 {%0, %1}, %2;" : "=f"(lo), "=f"(hi) : "l"(v));
}

// ---------------------------------------------------------------------------
// Kernel 1 (R12-proven): one CTA per class, block 512 = 4 row-streams.
// Gather row list (unrolled scan), 4 parallel accumulation streams, unroll 8.
// Writes q = EPS - sum/cnt'. CTA0 zeroes out.
// ---------------------------------------------------------------------------
__global__ __launch_bounds__(512) void k_accum(const float* __restrict__ x,
                                               const int* __restrict__ y,
                                               float* __restrict__ out,
                                               int m) {
    __shared__ unsigned short list[4096];
    __shared__ int cnt;
    __shared__ float partial[4 * D];

    int tid = threadIdx.x;
    int c   = blockIdx.x;
    if (tid == 0) cnt = 0;
    if (c == 0 && tid == 0) out[0] = 0.0f;
    __syncthreads();

#pragma unroll 8
    for (int i = tid; i < m; i += 512) {
        if (y[i] == c) {
            int p = atomicAdd(&cnt, 1);
            if (p < 4096) list[p] = (unsigned short)i;
        }
    }
    __syncthreads();
    int n = cnt < 4096 ? cnt : 4096;

    int j  = tid & (D - 1);
    int st = tid >> 7;                 // stream 0..3
    float acc = 0.0f;
#pragma unroll 8
    for (int k = st; k < n; k += 4) {
        acc += x[(size_t)list[k] * D + j];
    }
    partial[st * D + j] = acc;
    __syncthreads();
    if (tid < D) {
        float tot = partial[j] + partial[D + j] + partial[2 * D + j]
                  + partial[3 * D + j];
        float fc  = (n == 0) ? 1.0f : (float)n;
        g_q[c * D + j] = EPSF - tot / fc;
    }
}

// ---------------------------------------------------------------------------
// Kernel 2 (R10-proven, 19.7us): distances + log_softmax + NLL.
// block 256 = 8 warps; warp w: classes [8w, 8w+8); lane = sub*16 + trow;
// each lane: targets {trow, trow+16}, 4 classes. 6 LDS per j4 per warp.
// Math: FADD2 + free unpack + scalar FFMA with |src| modifier = 1.5 instr/el.
// ---------------------------------------------------------------------------
extern __shared__ float dynsmem[];

__global__ __launch_bounds__(256, 4) void k_loss(const float* __restrict__ x,
                                                 const int* __restrict__ y,
                                                 float* __restrict__ out,
                                                 int m) {
    float* xs = dynsmem;                   // 32 * 132 = 16.5 KB
    float* qs = xs + TGT * XS_STRIDE;      // 64 * 128 = 32 KB
    __shared__ float spmax[16 * TGT];
    __shared__ float spsum[16 * TGT];
    __shared__ float sdy[TGT];

    int tid = threadIdx.x;
    int i0  = blockIdx.x * TGT;

    // stage x target tile (32 x 128, coalesced float4)
    const float4* xg = (const float4*)(x + (size_t)(m + i0) * D);
#pragma unroll
    for (int k = 0; k < 4; k++) {
        int idx = tid + k * 256;
        int r = idx >> 5, c4 = idx & 31;
        *(float4*)&xs[r * XS_STRIDE + c4 * 4] = xg[r * 32 + c4];
    }
    // stage q
#pragma unroll
    for (int k = 0; k < 8; k++) {
        int idx = tid + k * 256;
        ((float4*)qs)[idx] = ((const float4*)g_q)[idx];
    }
    __syncthreads();

    int lane = tid & 31;
    int cg   = tid >> 5;                  // warp id 0..7
    int sub  = lane >> 4;                 // 0/1: class sub-group
    int trow = lane & 15;                 // target row 0..15
    int cb   = cg * 8 + sub * 4;          // first of this lane's 4 classes
    int sidx = cg * 2 + sub;              // class-subset index 0..15

    const ulonglong2* xr0 = (const ulonglong2*)&xs[trow * XS_STRIDE];
    const ulonglong2* xr1 = (const ulonglong2*)&xs[(trow + 16) * XS_STRIDE];
    const float* qb = &qs[cb * D];

    float acc[4][2];
#pragma unroll
    for (int k = 0; k < 4; k++) { acc[k][0] = 0.0f; acc[k][1] = 0.0f; }

#pragma unroll 2
    for (int j4 = 0; j4 < D / 4; j4++) {
        ulonglong2 xv0 = xr0[j4];
        ulonglong2 xv1 = xr1[j4];
#pragma unroll
        for (int cc = 0; cc < 4; cc++) {
            ulonglong2 qv = *(const ulonglong2*)&qb[cc * D + j4 * 4];
            unsigned long long a, b, e, f;
            add_f32x2(a, xv0.x, qv.x);     // target 0, dims 0-1
            add_f32x2(b, xv0.y, qv.y);     // target 0, dims 2-3
            add_f32x2(e, xv1.x, qv.x);     // target 1, dims 0-1
            add_f32x2(f, xv1.y, qv.y);     // target 1, dims 2-3
            float lo, hi;
            unpack2(lo, hi, a);
            acc[cc][0] = fmaf(lo, fabsf(lo), acc[cc][0]);
            acc[cc][0] = fmaf(hi, fabsf(hi), acc[cc][0]);
            unpack2(lo, hi, b);
            acc[cc][0] = fmaf(lo, fabsf(lo), acc[cc][0]);
            acc[cc][0] = fmaf(hi, fabsf(hi), acc[cc][0]);
            unpack2(lo, hi, e);
            acc[cc][1] = fmaf(lo, fabsf(lo), acc[cc][1]);
            acc[cc][1] = fmaf(hi, fabsf(hi), acc[cc][1]);
            unpack2(lo, hi, f);
            acc[cc][1] = fmaf(lo, fabsf(lo), acc[cc][1]);
            acc[cc][1] = fmaf(hi, fabsf(hi), acc[cc][1]);
        }
    }

    // partial softmax over this lane's 4 classes, for both targets
    float dist[4][2];
    float pm0 = -1e30f, pm1 = -1e30f;
#pragma unroll
    for (int cc = 0; cc < 4; cc++) {
        float d0 = acc[cc][0] * (-1.0f / (float)D);
        float d1 = acc[cc][1] * (-1.0f / (float)D);
        dist[cc][0] = d0; dist[cc][1] = d1;
        pm0 = fmaxf(pm0, d0);
        pm1 = fmaxf(pm1, d1);
    }
    spmax[sidx * TGT + trow]      = pm0;
    spmax[sidx * TGT + trow + 16] = pm1;
    __syncthreads();

    float g0 = -1e30f, g1 = -1e30f;
#pragma unroll
    for (int k = 0; k < 16; k++) {
        g0 = fmaxf(g0, spmax[k * TGT + trow]);
        g1 = fmaxf(g1, spmax[k * TGT + trow + 16]);
    }
    float se0 = 0.0f, se1 = 0.0f;
#pragma unroll
    for (int cc = 0; cc < 4; cc++) {
        se0 += __expf(dist[cc][0] - g0);
        se1 += __expf(dist[cc][1] - g1);
    }
    spsum[sidx * TGT + trow]      = se0;
    spsum[sidx * TGT + trow + 16] = se1;

    int yc0 = y[m + i0 + trow];
    if (yc0 >= cb && yc0 < cb + 4) sdy[trow] = dist[yc0 - cb][0];
    int yc1 = y[m + i0 + trow + 16];
    if (yc1 >= cb && yc1 < cb + 4) sdy[trow + 16] = dist[yc1 - cb][1];
    __syncthreads();

    if (tid < TGT) {
        float tot = 0.0f, gm = -1e30f;
#pragma unroll
        for (int k = 0; k < 16; k++) {
            tot += spsum[k * TGT + tid];
            gm   = fmaxf(gm, spmax[k * TGT + tid]);
        }
        float v = -(sdy[tid] - gm - __logf(tot));
#pragma unroll
        for (int off = 16; off > 0; off >>= 1)
            v += __shfl_xor_sync(0xFFFFFFFFu, v, off);
        if (tid == 0) atomicAdd(out, v / (float)m);
    }
}

// ---------------------------------------------------------------------------
// launch
// ---------------------------------------------------------------------------
extern "C" void kernel_launch(void* const* d_in, const int* in_sizes, int n_in,
                              void* d_out, int out_size) {
    const float* x = (const float*)d_in[0];
    const int*   y = (const int*)d_in[1];
    int n = in_sizes[1];
    int m = n / 2;
    float* out = (float*)d_out;

    k_accum<<<C, 512>>>(x, y, out, m);

    size_t dynbytes = (size_t)(TGT * XS_STRIDE + C * D) * sizeof(float);
    cudaFuncSetAttribute(k_loss, cudaFuncAttributeMaxDynamicSharedMemorySize,
                         (int)dynbytes);
    k_loss<<<m / TGT, 256, dynbytes>>>(x, y, out, m);
}